// round 3
// baseline (speedup 1.0000x reference)
#include <cuda_runtime.h>
#include <math.h>

#define NB 8
#define CC 256
#define HHH 56
#define WWW 56
#define SS 3136
#define CS 802816      // CC*SS
#define NCS 6422528    // NB*CC*SS

// ---------------- scratch (static device globals; no runtime alloc) ----------------
__device__ float g_t3[NCS];
__device__ float g_t5[NCS];
__device__ float g_t7[NCS];
__device__ float g_t17[NCS];
__device__ float g_t13[NCS];
__device__ float g_t8[NB * CC * CC];
__device__ float g_Amat[NB * CC * CC];
__device__ float g_t19T[NB * CC * CC];
__device__ float g_w7t[9 * CC * CC];   // [tap*256 + c][o]
__device__ float g_veff[CS];           // [c][s]
__device__ float g_t11[NB * SS];

// ---------------- stage A: t3 = (p2*x)^2 ; t5 = softmax_h(roll(t3,1,-1)) ----------------
// t5[n,c,h,w] = exp(t3[h-1, w+1] - m_{col w+1}) / sum_h exp(t3[:, w+1])
__global__ void __launch_bounds__(256) stageA(const float* __restrict__ x,
                                              const float* __restrict__ p2) {
    int plane = blockIdx.x;            // n*256 + c
    int c = plane & 255;
    const float* xp = x + (size_t)plane * SS;
    const float* pp = p2 + (size_t)c * SS;
    float* t3p = g_t3 + (size_t)plane * SS;
    float* t5p = g_t5 + (size_t)plane * SS;
    __shared__ float sm[SS];
    for (int i = threadIdx.x; i < SS; i += 256) {
        float v = pp[i] * xp[i];
        v *= v;
        sm[i] = v;
        t3p[i] = v;
    }
    __syncthreads();
    int wc = threadIdx.x;              // source column
    if (wc < WWW) {
        float mx = -1e30f;
        for (int h = 0; h < HHH; ++h) mx = fmaxf(mx, sm[h * WWW + wc]);
        float s = 0.f;
        for (int h = 0; h < HHH; ++h) {
            float e = __expf(sm[h * WWW + wc] - mx);
            sm[h * WWW + wc] = e;
            s += e;
        }
        float inv = 1.f / s;
        int wout = (wc + WWW - 1) % WWW;
        for (int h = 0; h < HHH; ++h) {
            int ho = h + 1; if (ho == HHH) ho = 0;
            t5p[ho * WWW + wout] = sm[h * WWW + wc] * inv;
        }
    }
}

// ---------------- prep: transpose w7 (C,9C) -> w7t[tap*256+c][o] ----------------
__global__ void prepW7(const float* __restrict__ w7) {
    int idx = blockIdx.x * 256 + threadIdx.x;     // over 9*256*256
    int o = idx & 255;
    int k = idx >> 8;                              // tap*256 + c
    int tap = k >> 8;
    int cc = k & 255;
    g_w7t[idx] = w7[o * 2304 + cc * 9 + tap];
}

// ---------------- prep: veff[c,s] = sum_o w6[o,c]*p9[o,s]*p11[o] ----------------
__global__ void prepVeff(const float* __restrict__ w6, const float* __restrict__ p9,
                         const float* __restrict__ p11) {
    int idx = blockIdx.x * 256 + threadIdx.x;     // c*SS + s
    int s = idx % SS;
    int c = idx / SS;
    float acc = 0.f;
#pragma unroll
    for (int o = 0; o < 32; ++o)
        acc = fmaf(w6[o * CC + c], p9[o * SS + s] * p11[o], acc);
    g_veff[idx] = acc;
}

// ---------------- t7: implicit GEMM, M=256(o) x N=3136(pix), K = 9 taps x 256 c ----------------
__global__ void __launch_bounds__(256) convT7(const float* __restrict__ x) {
    __shared__ float As[16][64];
    __shared__ float Bs[16][64];
    int n = blockIdx.z;
    int m0 = blockIdx.y * 64;
    int col0 = blockIdx.x * 64;
    int t = threadIdx.x;
    int tx = t & 15, ty = t >> 4;
    // B loader: pixel p = t&63, k-row base = t>>6
    int bp = t & 63;
    int bk = t >> 6;
    int pglob = col0 + bp;
    int h = pglob / 56, w = pglob - h * 56;
    const float* xn = x + (size_t)n * CS;
    // A loader: float4 along m
    int am4 = (t & 15) * 4;
    int ak = t >> 4;
    float acc[4][4] = {};
    for (int tap = 0; tap < 9; ++tap) {
        int dy = (tap / 3) * 3 - 3;
        int dx = (tap % 3) * 3 - 3;
        int hh = h + dy, ww = w + dx;
        bool valid = ((unsigned)hh < 56u) && ((unsigned)ww < 56u);
        int poff = hh * 56 + ww;
        for (int c0 = 0; c0 < 256; c0 += 16) {
            float4 a = *(const float4*)&g_w7t[(size_t)(tap * 256 + c0 + ak) * 256 + m0 + am4];
            float bv[4];
#pragma unroll
            for (int ps = 0; ps < 4; ++ps) {
                int kr = bk + 4 * ps;
                bv[ps] = valid ? xn[(size_t)(c0 + kr) * SS + poff] : 0.f;
            }
            __syncthreads();
            *(float4*)&As[ak][am4] = a;
#pragma unroll
            for (int ps = 0; ps < 4; ++ps) Bs[bk + 4 * ps][bp] = bv[ps];
            __syncthreads();
#pragma unroll
            for (int kk = 0; kk < 16; ++kk) {
                float av[4], bw[4];
                *(float4*)av = *(const float4*)&As[kk][ty * 4];
                *(float4*)bw = *(const float4*)&Bs[kk][tx * 4];
#pragma unroll
                for (int i = 0; i < 4; ++i)
#pragma unroll
                    for (int j = 0; j < 4; ++j) acc[i][j] = fmaf(av[i], bw[j], acc[i][j]);
            }
        }
    }
    float* t7n = g_t7 + (size_t)n * CS;
#pragma unroll
    for (int i = 0; i < 4; ++i) {
        int row = m0 + ty * 4 + i;
        float4 r = make_float4(acc[i][0], acc[i][1], acc[i][2], acc[i][3]);
        *(float4*)&t7n[(size_t)row * SS + col0 + tx * 4] = r;
    }
}

// ---------------- generic NN GEMM, M=256, K=256, 64x64 tiles ----------------
// MODE 0: B = x with roll(+1,h), out t17 = t3 - acc                 (N=3136)
// MODE 1: B = t13, out = s_c*acc + t7*t17 -> final output           (N=3136)
// MODE 2: B = t8 (ld 256), out transposed, scaled by s_hw -> t19T   (N=256)
template <int MODE>
__global__ void __launch_bounds__(256) gemmNN(const float* __restrict__ A,
                                              const float* __restrict__ B,
                                              float* __restrict__ Out,
                                              const float* __restrict__ E1,
                                              const float* __restrict__ E2,
                                              size_t strA, size_t strB) {
    constexpr int LDB = (MODE == 2) ? 256 : SS;
    constexpr size_t strO = (MODE == 2) ? (size_t)65536 : (size_t)CS;
    __shared__ float As[16][68];
    __shared__ float Bs[16][64];
    int n = blockIdx.z;
    int m0 = blockIdx.y * 64;
    int col0 = blockIdx.x * 64;
    const float* An = A + (size_t)n * strA;
    const float* Bn = B + (size_t)n * strB;
    int t = threadIdx.x;
    int tx = t & 15, ty = t >> 4;
    int am = t >> 2;
    int akq = (t & 3) * 4;
    int bp = t & 63;
    int bk = t >> 6;
    int pglob = col0 + bp;
    int poff;
    if (MODE == 0) {
        int h = pglob / 56, w = pglob - h * 56;
        int h2 = h ? h - 1 : 55;     // t14[h] = x[h-1 mod 56]
        poff = h2 * 56 + w;
    } else {
        poff = pglob;
    }
    float acc[4][4] = {};
    for (int k0 = 0; k0 < 256; k0 += 16) {
        float4 a = *(const float4*)&An[(size_t)(m0 + am) * 256 + k0 + akq];
        float bv[4];
#pragma unroll
        for (int ps = 0; ps < 4; ++ps)
            bv[ps] = Bn[(size_t)(k0 + bk + 4 * ps) * LDB + poff];
        __syncthreads();
        As[akq + 0][am] = a.x;
        As[akq + 1][am] = a.y;
        As[akq + 2][am] = a.z;
        As[akq + 3][am] = a.w;
#pragma unroll
        for (int ps = 0; ps < 4; ++ps) Bs[bk + 4 * ps][bp] = bv[ps];
        __syncthreads();
#pragma unroll
        for (int kk = 0; kk < 16; ++kk) {
            float av[4], bw[4];
            *(float4*)av = *(const float4*)&As[kk][ty * 4];
            *(float4*)bw = *(const float4*)&Bs[kk][tx * 4];
#pragma unroll
            for (int i = 0; i < 4; ++i)
#pragma unroll
                for (int j = 0; j < 4; ++j) acc[i][j] = fmaf(av[i], bw[j], acc[i][j]);
        }
    }
    if (MODE == 0) {
        const float* e1 = E1 + (size_t)n * CS;   // t3
        float* on = Out + (size_t)n * strO;
#pragma unroll
        for (int i = 0; i < 4; ++i) {
            size_t idx = (size_t)(m0 + ty * 4 + i) * SS + col0 + tx * 4;
            float4 e = *(const float4*)&e1[idx];
            float4 r = make_float4(e.x - acc[i][0], e.y - acc[i][1],
                                   e.z - acc[i][2], e.w - acc[i][3]);
            *(float4*)&on[idx] = r;
        }
    } else if (MODE == 1) {
        const float* e1 = E1 + (size_t)n * CS;   // t7
        const float* e2 = E2 + (size_t)n * CS;   // t17
        float* on = Out + (size_t)n * strO;
        const float sc = 0.0625f;                // 1/sqrt(256)
#pragma unroll
        for (int i = 0; i < 4; ++i) {
            size_t idx = (size_t)(m0 + ty * 4 + i) * SS + col0 + tx * 4;
            float4 a7 = *(const float4*)&e1[idx];
            float4 a17 = *(const float4*)&e2[idx];
            float4 r;
            r.x = fmaf(sc, acc[i][0], a7.x * a17.x);
            r.y = fmaf(sc, acc[i][1], a7.y * a17.y);
            r.z = fmaf(sc, acc[i][2], a7.z * a17.z);
            r.w = fmaf(sc, acc[i][3], a7.w * a17.w);
            *(float4*)&on[idx] = r;
        }
    } else {
        float* on = Out + (size_t)n * strO;
        const float shw = 1.f / 56.f;
#pragma unroll
        for (int i = 0; i < 4; ++i)
#pragma unroll
            for (int j = 0; j < 4; ++j)
                on[(size_t)(col0 + tx * 4 + j) * 256 + m0 + ty * 4 + i] = acc[i][j] * shw;
    }
}

// ---------------- NT GEMM: C[m,n] = scale * sum_k A[m,k]*B[n,k], M=N=256, K=3136 ----------------
__global__ void __launch_bounds__(256) gemmNT(const float* __restrict__ A,
                                              const float* __restrict__ B,
                                              float* __restrict__ Out,
                                              size_t strA, size_t strB, float scale) {
    __shared__ float As[16][68];
    __shared__ float Bs[16][68];
    int n = blockIdx.z;
    const float* An = A + (size_t)n * strA;
    const float* Bn = B + (size_t)n * strB;
    float* On = Out + (size_t)n * 65536;
    int m0 = blockIdx.y * 64, n0 = blockIdx.x * 64;
    int t = threadIdx.x;
    int tx = t & 15, ty = t >> 4;
    int r = t >> 2;
    int kq = (t & 3) * 4;
    float acc[4][4] = {};
    for (int k0 = 0; k0 < SS; k0 += 16) {
        float4 a = *(const float4*)&An[(size_t)(m0 + r) * SS + k0 + kq];
        float4 b = *(const float4*)&Bn[(size_t)(n0 + r) * SS + k0 + kq];
        __syncthreads();
        As[kq + 0][r] = a.x; As[kq + 1][r] = a.y; As[kq + 2][r] = a.z; As[kq + 3][r] = a.w;
        Bs[kq + 0][r] = b.x; Bs[kq + 1][r] = b.y; Bs[kq + 2][r] = b.z; Bs[kq + 3][r] = b.w;
        __syncthreads();
#pragma unroll
        for (int kk = 0; kk < 16; ++kk) {
            float av[4], bw[4];
            *(float4*)av = *(const float4*)&As[kk][ty * 4];
            *(float4*)bw = *(const float4*)&Bs[kk][tx * 4];
#pragma unroll
            for (int i = 0; i < 4; ++i)
#pragma unroll
                for (int j = 0; j < 4; ++j) acc[i][j] = fmaf(av[i], bw[j], acc[i][j]);
        }
    }
#pragma unroll
    for (int i = 0; i < 4; ++i) {
        float4 rr = make_float4(acc[i][0] * scale, acc[i][1] * scale,
                                acc[i][2] * scale, acc[i][3] * scale);
        *(float4*)&On[(size_t)(m0 + ty * 4 + i) * 256 + n0 + tx * 4] = rr;
    }
}

// ---------------- t11[n,s] = sum_c t3[n,c,s]*veff[c,s] ----------------
__global__ void calcT11() {
    int idx = blockIdx.x * 256 + threadIdx.x;   // n*SS + s
    int n = idx / SS;
    int s = idx - n * SS;
    const float* t3n = g_t3 + (size_t)n * CS + s;
    const float* vf = g_veff + s;
    float acc = 0.f;
#pragma unroll 8
    for (int c = 0; c < CC; ++c)
        acc = fmaf(t3n[(size_t)c * SS], vf[(size_t)c * SS], acc);
    g_t11[idx] = acc;
}

// ---------------- t13 = t11 - dwconv3x1_d2(max(t5,t7)) ----------------
__global__ void calcT13(const float* __restrict__ w12) {
    int idx = blockIdx.x * 256 + threadIdx.x;   // n*CC*SS + c*SS + p
    int p = idx % SS;
    int nc = idx / SS;
    int c = nc & 255;
    int n = nc >> 8;
    int h = p / 56, w = p - h * 56;
    float acc = 0.f;
#pragma unroll
    for (int r = 0; r < 3; ++r) {
        int hh = h + 2 * r - 2;
        if ((unsigned)hh < 56u) {
            size_t q = (size_t)nc * SS + hh * 56 + w;
            acc = fmaf(w12[c * 3 + r], fmaxf(g_t5[q], g_t7[q]), acc);
        }
    }
    g_t13[idx] = g_t11[(size_t)n * SS + p] - acc;
}

// ---------------- launch ----------------
extern "C" void kernel_launch(void* const* d_in, const int* in_sizes, int n_in,
                              void* d_out, int out_size) {
    const float* x   = (const float*)d_in[0];
    const float* p2  = (const float*)d_in[1];
    const float* w6  = (const float*)d_in[2];
    const float* w7  = (const float*)d_in[3];
    const float* p9  = (const float*)d_in[4];
    const float* p11 = (const float*)d_in[5];
    const float* w12 = (const float*)d_in[6];
    const float* w15 = (const float*)d_in[7];
    const float* p16 = (const float*)d_in[8];
    float* out = (float*)d_out;

    void *t3p, *t5p, *t7p, *t17p, *t13p, *t8p, *Amatp, *t19Tp;
    cudaGetSymbolAddress(&t3p, g_t3);
    cudaGetSymbolAddress(&t5p, g_t5);
    cudaGetSymbolAddress(&t7p, g_t7);
    cudaGetSymbolAddress(&t17p, g_t17);
    cudaGetSymbolAddress(&t13p, g_t13);
    cudaGetSymbolAddress(&t8p, g_t8);
    cudaGetSymbolAddress(&Amatp, g_Amat);
    cudaGetSymbolAddress(&t19Tp, g_t19T);

    // stage A: t3, t5
    stageA<<<NB * CC, 256>>>(x, p2);
    // weight prep (independent)
    prepW7<<<9 * CC, 256>>>(w7);
    prepVeff<<<SS, 256>>>(w6, p9, p11);
    // t7: big implicit-GEMM conv
    convT7<<<dim3(49, 4, NB), 256>>>(x);
    // t17 = t3 - w15 @ roll(x, +1, h)
    gemmNN<0><<<dim3(49, 4, NB), 256>>>(w15, x, (float*)t17p, (const float*)t3p, nullptr,
                                        0, (size_t)CS);
    // t8 = s_hw * t5 @ t3^T
    gemmNT<<<dim3(4, 4, NB), 256>>>((const float*)t5p, (const float*)t3p, (float*)t8p,
                                    (size_t)CS, (size_t)CS, 1.f / 56.f);
    // t11
    calcT11<<<(NB * SS) / 256, 256>>>();
    // t13
    calcT13<<<NCS / 256, 256>>>(w12);
    // Amat = t17 @ p16^T
    gemmNT<<<dim3(4, 4, NB), 256>>>((const float*)t17p, p16, (float*)Amatp,
                                    (size_t)CS, 0, 1.f);
    // t19T[c][d] = t19[d][c]; t19 = s_hw * Amat @ t8  (transposed write)
    gemmNN<2><<<dim3(4, 4, NB), 256>>>((const float*)Amatp, (const float*)t8p,
                                       (float*)t19Tp, nullptr, nullptr,
                                       (size_t)65536, (size_t)65536);
    // out = s_c * t19^T @ t13 + t7 * t17
    gemmNN<1><<<dim3(49, 4, NB), 256>>>((const float*)t19Tp, (const float*)t13p, out,
                                        (const float*)t7p, (const float*)t17p,
                                        (size_t)65536, (size_t)CS);
}